// round 10
// baseline (speedup 1.0000x reference)
#include <cuda_runtime.h>
#include <cuda_fp16.h>
#include <cuda_bf16.h>
#include <math.h>

// Problem constants
#define B     256
#define V     100
#define C     40
#define E     128
#define H     100
#define G4    400      // 4*H
#define M_TOT 32768    // B*E

// ---------------- device scratch ----------------
__device__ int   g_last[B];                          // built via atomicMax (idempotent)
__device__ __align__(16) float g_xseq[B * V * E];    // A[32768][100]
__device__ __align__(16) float g_xpart[M_TOT * G4];  // x @ W_ih^T + biases
__device__ float g_trueh[B * E];

// ---------------- helpers ----------------
__device__ __forceinline__ unsigned f2tf32(float f) {
    unsigned r;
    asm("cvt.rna.tf32.f32 %0, %1;" : "=r"(r) : "f"(f));
    return r;
}
__device__ __forceinline__ void mma8(float* d, const unsigned* a,
                                     unsigned b0, unsigned b1) {
    asm("mma.sync.aligned.m16n8k8.row.col.f32.tf32.tf32.f32 "
        "{%0,%1,%2,%3},{%4,%5,%6,%7},{%8,%9},{%0,%1,%2,%3};"
        : "+f"(d[0]), "+f"(d[1]), "+f"(d[2]), "+f"(d[3])
        : "r"(a[0]), "r"(a[1]), "r"(a[2]), "r"(a[3]), "r"(b0), "r"(b1));
}
__device__ __forceinline__ float tanhapx(float x) {
    float r;
    asm("tanh.approx.f32 %0, %1;" : "=f"(r) : "f"(x));
    return r;
}
__device__ __forceinline__ float sigt(float x) {
    return fmaf(0.5f, tanhapx(0.5f * x), 0.5f);
}

// ---------------- K1: masked embedding sum + fused last-visit ----------
// One warp per (b,v); lane holds 4 of 128 embed dims as float4.
// All lanes read the same 40 mask values (broadcast) -> lane 0 knows
// whether this visit has any unmasked code and atomicMax's g_last[b].
// atomicMax is idempotent across graph replays (same data -> same max).
__global__ void k_embed(const int* __restrict__ diag,
                        const float* __restrict__ mask,
                        const float* __restrict__ table) {
    int flag = 0;
    if (threadIdx.x < 64) flag = diag[2 * threadIdx.x + 1];
    int is64 = __syncthreads_or(flag != 0) ? 0 : 1;

    int p    = blockIdx.x * 8 + (threadIdx.x >> 5);   // (b*V + v)
    int lane = threadIdx.x & 31;
    int b    = p / V;
    int v    = p - b * V;
    const float4* tab4 = (const float4*)table;
    float4 acc = make_float4(0.f, 0.f, 0.f, 0.f);
    bool has = false;
    int base = p * C;
    #pragma unroll
    for (int c4 = 0; c4 < C / 4; c4++) {
        float4 m4 = *(const float4*)(mask + base + c4 * 4);
        int code[4];
        #pragma unroll
        for (int q = 0; q < 4; q++)
            code[q] = diag[(base + c4 * 4 + q) << is64];
        float mm[4] = {m4.x, m4.y, m4.z, m4.w};
        #pragma unroll
        for (int q = 0; q < 4; q++) {
            has |= (mm[q] != 0.f);
            float4 t = tab4[code[q] * 32 + lane];
            acc.x += t.x * mm[q]; acc.y += t.y * mm[q];
            acc.z += t.z * mm[q]; acc.w += t.w * mm[q];
        }
    }
    ((float4*)g_xseq)[p * 32 + lane] = acc;
    if (lane == 0 && has) atomicMax(&g_last[b], v);
}

// ---------------- K2: single-TF32 tensor GEMM ----------------
// x_part[32768,400] = A[32768,100] @ W[400,100]^T + (b_ih + b_hh)
#define BMg 128
#define BNg 80
#define SST 36

__global__ void __launch_bounds__(256, 2) k_gemm(const float* __restrict__ W,
                                                 const float* __restrict__ bih,
                                                 const float* __restrict__ bhh) {
    __shared__ unsigned As[BMg * SST];   // tf32 A tile [m][k]
    __shared__ unsigned Ws[BNg * SST];   // tf32 W tile [n][k]

    int tid = threadIdx.x;
    int wid = tid >> 5, lane = tid & 31;
    int wm = wid & 3, wn = wid >> 2;
    int g = lane >> 2, t = lane & 3;
    int m0 = blockIdx.x * BMg;
    int n0 = blockIdx.y * BNg;

    float d[2][5][4];
    #pragma unroll
    for (int ni = 0; ni < 5; ni++) {
        int cc = n0 + wn * 40 + ni * 8 + 2 * t;
        float b0 = bih[cc] + bhh[cc];
        float b1 = bih[cc + 1] + bhh[cc + 1];
        #pragma unroll
        for (int mi = 0; mi < 2; mi++) {
            d[mi][ni][0] = b0; d[mi][ni][1] = b1;
            d[mi][ni][2] = b0; d[mi][ni][3] = b1;
        }
    }

    #pragma unroll 1
    for (int kc = 0; kc < 4; kc++) {
        int k0 = kc * 32;
        #pragma unroll
        for (int i = 0; i < 16; i++) {
            int li = i * 256 + tid;
            int m = li >> 5, k = li & 31;
            float v = (k0 + k < 100) ? g_xseq[(m0 + m) * 100 + k0 + k] : 0.f;
            As[m * SST + k] = f2tf32(v);
        }
        #pragma unroll
        for (int i = 0; i < 10; i++) {
            int li = i * 256 + tid;
            int n = li >> 5, k = li & 31;
            float w = (k0 + k < 100) ? W[(n0 + n) * 100 + k0 + k] : 0.f;
            Ws[n * SST + k] = f2tf32(w);
        }
        __syncthreads();

        int ns = (kc == 3) ? 1 : 4;      // last chunk covers k 96..99 only
        #pragma unroll
        for (int s = 0; s < 4; s++) {
            if (s >= ns) break;
            unsigned a[2][4];
            #pragma unroll
            for (int mi = 0; mi < 2; mi++) {
                int r = (wm * 32 + mi * 16 + g) * SST + s * 8 + t;
                a[mi][0] = As[r];
                a[mi][1] = As[r + 8 * SST];
                a[mi][2] = As[r + 4];
                a[mi][3] = As[r + 8 * SST + 4];
            }
            #pragma unroll
            for (int ni = 0; ni < 5; ni++) {
                int rb = (wn * 40 + ni * 8 + g) * SST + s * 8 + t;
                unsigned b0 = Ws[rb], b1 = Ws[rb + 4];
                #pragma unroll
                for (int mi = 0; mi < 2; mi++)
                    mma8(d[mi][ni], a[mi], b0, b1);
            }
        }
        __syncthreads();
    }

    #pragma unroll
    for (int mi = 0; mi < 2; mi++) {
        int r = m0 + wm * 32 + mi * 16 + g;
        #pragma unroll
        for (int ni = 0; ni < 5; ni++) {
            int cc = n0 + wn * 40 + ni * 8 + 2 * t;
            *(float2*)&g_xpart[r * G4 + cc]       = make_float2(d[mi][ni][0], d[mi][ni][1]);
            *(float2*)&g_xpart[(r + 8) * G4 + cc] = make_float2(d[mi][ni][2], d[mi][ni][3]);
        }
    }
}

// ---------------- K3: fp16 recurrence, TWO embed-rows per CTA ------------
// Weights w2[52] are e-independent -> one CTA runs rows e0,e0+1 with the
// same registers; per-step barriers/phase2 amortized over 2 rows.
// 416 thr, thread g handles gate g for both rows.
__global__ void __launch_bounds__(416, 1) k_rec(const float* __restrict__ Whh) {
    __shared__ __align__(16) __half h_h[2][104];   // [row][unit], + zero pad
    __shared__ float gates_s[2][G4];
    __shared__ int   last_s[B];

    int tid = threadIdx.x;
    int e0  = blockIdx.x * 2;
    int g   = tid;                        // gate index (valid < 400)
    int gc  = (g < G4) ? g : (G4 - 1);    // clamped for safe gmem addressing

    __half2 w2[52];
    #pragma unroll
    for (int j = 0; j < 50; j++) {
        float lo = 0.f, hi = 0.f;
        if (g < G4) {
            lo = Whh[g * 100 + 2 * j];
            hi = Whh[g * 100 + 2 * j + 1];
        }
        w2[j] = __floats2half2_rn(lo, hi);
    }
    w2[50] = __floats2half2_rn(0.f, 0.f);
    w2[51] = __floats2half2_rn(0.f, 0.f);

    for (int i = tid; i < B; i += 416) last_s[i] = g_last[i];
    if (tid < 104) {
        h_h[0][tid] = __float2half_rn(0.f);
        h_h[1][tid] = __float2half_rn(0.f);
    }
    float c0 = 0.f, c1 = 0.f;
    __syncthreads();

    const float* xp0 = g_xpart + e0 * G4 + gc;    // row e0; row e1 = +G4
    float* th = g_trueh + e0;
    const float4* hv0p = (const float4*)h_h[0];
    const float4* hv1p = (const float4*)h_h[1];

    float xv0n = __ldg(xp0);
    float xv1n = __ldg(xp0 + G4);

    #pragma unroll 1
    for (int t = 0; t < B; t++) {
        float xv0 = xv0n, xv1 = xv1n;
        int tn = (t + 1 < B) ? (t + 1) : (B - 1);
        xv0n = __ldg(xp0 + tn * (E * G4));
        xv1n = __ldg(xp0 + tn * (E * G4) + G4);

        __half2 z = __floats2half2_rn(0.f, 0.f);
        __half2 a00 = z, a01 = z, a02 = z, a03 = z;
        __half2 a10 = z, a11 = z, a12 = z, a13 = z;
        #pragma unroll
        for (int j = 0; j < 13; j++) {
            float4 hv0 = hv0p[j];
            float4 hv1 = hv1p[j];
            a00 = __hfma2(w2[4 * j + 0], *(__half2*)&hv0.x, a00);
            a10 = __hfma2(w2[4 * j + 0], *(__half2*)&hv1.x, a10);
            a01 = __hfma2(w2[4 * j + 1], *(__half2*)&hv0.y, a01);
            a11 = __hfma2(w2[4 * j + 1], *(__half2*)&hv1.y, a11);
            a02 = __hfma2(w2[4 * j + 2], *(__half2*)&hv0.z, a02);
            a12 = __hfma2(w2[4 * j + 2], *(__half2*)&hv1.z, a12);
            a03 = __hfma2(w2[4 * j + 3], *(__half2*)&hv0.w, a03);
            a13 = __hfma2(w2[4 * j + 3], *(__half2*)&hv1.w, a13);
        }
        float2 p00 = __half22float2(a00), p01 = __half22float2(a01);
        float2 p02 = __half22float2(a02), p03 = __half22float2(a03);
        float2 p10 = __half22float2(a10), p11 = __half22float2(a11);
        float2 p12 = __half22float2(a12), p13 = __half22float2(a13);
        float dot0 = ((p00.x + p00.y) + (p01.x + p01.y)) +
                     ((p02.x + p02.y) + (p03.x + p03.y));
        float dot1 = ((p10.x + p10.y) + (p11.x + p11.y)) +
                     ((p12.x + p12.y) + (p13.x + p13.y));

        if (g < G4) {
            float pre0 = dot0 + xv0;
            float pre1 = dot1 + xv1;
            bool isg = (g >= 200 && g < 300);
            gates_s[0][g] = isg ? tanhapx(pre0) : sigt(pre0);
            gates_s[1][g] = isg ? tanhapx(pre1) : sigt(pre1);
        }
        __syncthreads();

        if (tid < H) {
            float iv0 = gates_s[0][tid];
            float fv0 = gates_s[0][H + tid];
            float gv0 = gates_s[0][2 * H + tid];
            float ov0 = gates_s[0][3 * H + tid];
            c0 = fv0 * c0 + iv0 * gv0;
            float h0 = ov0 * tanhapx(c0);
            h_h[0][tid] = __float2half_rn(h0);

            float iv1 = gates_s[1][tid];
            float fv1 = gates_s[1][H + tid];
            float gv1 = gates_s[1][2 * H + tid];
            float ov1 = gates_s[1][3 * H + tid];
            c1 = fv1 * c1 + iv1 * gv1;
            float h1 = ov1 * tanhapx(c1);
            h_h[1][tid] = __float2half_rn(h1);

            if (tid == last_s[t]) {
                th[t * E]     = h0;
                th[t * E + 1] = h1;
            }
        }
        __syncthreads();
    }
}

// ---------------- K4: final FC + sigmoid ----------------
__global__ void k_fc(const float* __restrict__ fcw,
                     const float* __restrict__ fcb,
                     float* __restrict__ out) {
    int warp = (blockIdx.x * blockDim.x + threadIdx.x) >> 5;
    int lane = threadIdx.x & 31;
    if (warp >= B) return;
    const float* th = g_trueh + warp * E;
    float acc = 0.f;
    #pragma unroll
    for (int k = 0; k < 4; k++) acc += th[lane + 32 * k] * fcw[lane + 32 * k];
    #pragma unroll
    for (int s = 16; s > 0; s >>= 1) acc += __shfl_down_sync(0xFFFFFFFFu, acc, s);
    if (lane == 0) out[warp] = sigt(acc + fcb[0]);
}

// ---------------- launcher: kernel launches ONLY ----------------
extern "C" void kernel_launch(void* const* d_in, const int* in_sizes, int n_in,
                              void* d_out, int out_size) {
    const int*   diag = (const int*)d_in[0];
    const float* mask = (const float*)d_in[1];
    const float* tab  = (const float*)d_in[2];
    const float* Wih  = (const float*)d_in[3];
    const float* Whh  = (const float*)d_in[4];
    const float* bih  = (const float*)d_in[5];
    const float* bhh  = (const float*)d_in[6];
    const float* fcw  = (const float*)d_in[7];
    const float* fcb  = (const float*)d_in[8];
    float* out = (float*)d_out;

    (void)in_sizes; (void)n_in; (void)out_size;

    k_embed<<<(B * V) / 8, 256>>>(diag, mask, tab);
    k_gemm<<<dim3(M_TOT / BMg, G4 / BNg), 256>>>(Wih, bih, bhh);
    k_rec<<<E / 2, 416>>>(Whh);
    k_fc<<<32, 256>>>(fcw, fcb, out);
}

// round 11
// speedup vs baseline: 1.5234x; 1.5234x over previous
#include <cuda_runtime.h>
#include <cuda_fp16.h>
#include <cuda_bf16.h>
#include <math.h>

// Problem constants
#define B     256
#define V     100
#define C     40
#define E     128
#define H     100
#define G4    400      // 4*H
#define M_TOT 32768    // B*E

// ---------------- device scratch ----------------
__device__ int   g_last[B];                          // built via atomicMax (idempotent)
__device__ __align__(16) float g_xseq[B * V * E];    // A[32768][100]
__device__ __align__(16) float g_xpart[M_TOT * G4];  // x @ W_ih^T + biases
__device__ float g_trueh[B * E];

// ---------------- helpers ----------------
__device__ __forceinline__ unsigned f2tf32(float f) {
    unsigned r;
    asm("cvt.rna.tf32.f32 %0, %1;" : "=r"(r) : "f"(f));
    return r;
}
__device__ __forceinline__ void mma8(float* d, const unsigned* a,
                                     unsigned b0, unsigned b1) {
    asm("mma.sync.aligned.m16n8k8.row.col.f32.tf32.tf32.f32 "
        "{%0,%1,%2,%3},{%4,%5,%6,%7},{%8,%9},{%0,%1,%2,%3};"
        : "+f"(d[0]), "+f"(d[1]), "+f"(d[2]), "+f"(d[3])
        : "r"(a[0]), "r"(a[1]), "r"(a[2]), "r"(a[3]), "r"(b0), "r"(b1));
}
__device__ __forceinline__ float tanhapx(float x) {
    float r;
    asm("tanh.approx.f32 %0, %1;" : "=f"(r) : "f"(x));
    return r;
}
__device__ __forceinline__ float sigt(float x) {
    return fmaf(0.5f, tanhapx(0.5f * x), 0.5f);
}

// ---------------- K1: masked embedding sum + fused last-visit ----------
__global__ void k_embed(const int* __restrict__ diag,
                        const float* __restrict__ mask,
                        const float* __restrict__ table) {
    int flag = 0;
    if (threadIdx.x < 64) flag = diag[2 * threadIdx.x + 1];
    int is64 = __syncthreads_or(flag != 0) ? 0 : 1;

    int p    = blockIdx.x * 8 + (threadIdx.x >> 5);   // (b*V + v)
    int lane = threadIdx.x & 31;
    int b    = p / V;
    int v    = p - b * V;
    const float4* tab4 = (const float4*)table;
    float4 acc = make_float4(0.f, 0.f, 0.f, 0.f);
    bool has = false;
    int base = p * C;
    #pragma unroll
    for (int c4 = 0; c4 < C / 4; c4++) {
        float4 m4 = *(const float4*)(mask + base + c4 * 4);
        int code[4];
        #pragma unroll
        for (int q = 0; q < 4; q++)
            code[q] = diag[(base + c4 * 4 + q) << is64];
        float mm[4] = {m4.x, m4.y, m4.z, m4.w};
        #pragma unroll
        for (int q = 0; q < 4; q++) {
            has |= (mm[q] != 0.f);
            float4 t = tab4[code[q] * 32 + lane];
            acc.x += t.x * mm[q]; acc.y += t.y * mm[q];
            acc.z += t.z * mm[q]; acc.w += t.w * mm[q];
        }
    }
    ((float4*)g_xseq)[p * 32 + lane] = acc;
    if (lane == 0 && has) atomicMax(&g_last[b], v);
}

// ---------------- K2: single-TF32 tensor GEMM ----------------
#define BMg 128
#define BNg 80
#define SST 36

__global__ void __launch_bounds__(256, 2) k_gemm(const float* __restrict__ W,
                                                 const float* __restrict__ bih,
                                                 const float* __restrict__ bhh) {
    __shared__ unsigned As[BMg * SST];
    __shared__ unsigned Ws[BNg * SST];

    int tid = threadIdx.x;
    int wid = tid >> 5, lane = tid & 31;
    int wm = wid & 3, wn = wid >> 2;
    int g = lane >> 2, t = lane & 3;
    int m0 = blockIdx.x * BMg;
    int n0 = blockIdx.y * BNg;

    float d[2][5][4];
    #pragma unroll
    for (int ni = 0; ni < 5; ni++) {
        int cc = n0 + wn * 40 + ni * 8 + 2 * t;
        float b0 = bih[cc] + bhh[cc];
        float b1 = bih[cc + 1] + bhh[cc + 1];
        #pragma unroll
        for (int mi = 0; mi < 2; mi++) {
            d[mi][ni][0] = b0; d[mi][ni][1] = b1;
            d[mi][ni][2] = b0; d[mi][ni][3] = b1;
        }
    }

    #pragma unroll 1
    for (int kc = 0; kc < 4; kc++) {
        int k0 = kc * 32;
        #pragma unroll
        for (int i = 0; i < 16; i++) {
            int li = i * 256 + tid;
            int m = li >> 5, k = li & 31;
            float v = (k0 + k < 100) ? g_xseq[(m0 + m) * 100 + k0 + k] : 0.f;
            As[m * SST + k] = f2tf32(v);
        }
        #pragma unroll
        for (int i = 0; i < 10; i++) {
            int li = i * 256 + tid;
            int n = li >> 5, k = li & 31;
            float w = (k0 + k < 100) ? W[(n0 + n) * 100 + k0 + k] : 0.f;
            Ws[n * SST + k] = f2tf32(w);
        }
        __syncthreads();

        int ns = (kc == 3) ? 1 : 4;
        #pragma unroll
        for (int s = 0; s < 4; s++) {
            if (s >= ns) break;
            unsigned a[2][4];
            #pragma unroll
            for (int mi = 0; mi < 2; mi++) {
                int r = (wm * 32 + mi * 16 + g) * SST + s * 8 + t;
                a[mi][0] = As[r];
                a[mi][1] = As[r + 8 * SST];
                a[mi][2] = As[r + 4];
                a[mi][3] = As[r + 8 * SST + 4];
            }
            #pragma unroll
            for (int ni = 0; ni < 5; ni++) {
                int rb = (wn * 40 + ni * 8 + g) * SST + s * 8 + t;
                unsigned b0 = Ws[rb], b1 = Ws[rb + 4];
                #pragma unroll
                for (int mi = 0; mi < 2; mi++)
                    mma8(d[mi][ni], a[mi], b0, b1);
            }
        }
        __syncthreads();
    }

    #pragma unroll
    for (int mi = 0; mi < 2; mi++) {
        int r = m0 + wm * 32 + mi * 16 + g;
        #pragma unroll
        for (int ni = 0; ni < 5; ni++) {
            int cc = n0 + wn * 40 + ni * 8 + 2 * t;
            *(float2*)&g_xpart[r * G4 + cc]       = make_float2(d[mi][ni][0], d[mi][ni][1]);
            *(float2*)&g_xpart[(r + 8) * G4 + cc] = make_float2(d[mi][ni][2], d[mi][ni][3]);
        }
    }
}

// ---------------- K3: in-warp-unit fp16 recurrence, 1 CTA per e-row ------
// 416 thr = 13 warps. Warp w owns units 8w..8w+7; lane = uiw*4 + gt.
// All 4 gates of a unit are in ONE warp: gate exchange = STS + syncwarp +
// one broadcast LDS.128. Cell update redundant across the quad (cheap with
// tanh.approx). h double-buffered -> ONE __syncthreads per step.
__global__ void __launch_bounds__(416, 1) k_rec(const float* __restrict__ Whh) {
    __shared__ __align__(16) __half hbuf[2][104];   // h[0..99] + zero pad
    __shared__ __align__(16) float  gwarp[416];     // per-warp gate slots
    __shared__ int last_s[B];

    int tid  = threadIdx.x;
    int e    = blockIdx.x;
    int w    = tid >> 5;
    int lane = tid & 31;
    int uiw  = lane >> 2;             // unit-in-warp 0..7
    int gt   = lane & 3;              // 0=i 1=f 2=g 3=o
    int u    = w * 8 + uiw;           // unit 0..103 (valid < 100)
    bool valid = (u < H);
    int grow = gt * H + (valid ? u : (H - 1));   // clamped gate row

    // 52 half2 weight regs (zeros if invalid/pad)
    __half2 w2[52];
    #pragma unroll
    for (int j = 0; j < 50; j++) {
        float lo = 0.f, hi = 0.f;
        if (valid) {
            lo = Whh[grow * 100 + 2 * j];
            hi = Whh[grow * 100 + 2 * j + 1];
        }
        w2[j] = __floats2half2_rn(lo, hi);
    }
    w2[50] = __floats2half2_rn(0.f, 0.f);
    w2[51] = __floats2half2_rn(0.f, 0.f);

    for (int i = tid; i < B; i += 416) last_s[i] = g_last[i];
    if (tid < 104) {
        hbuf[0][tid] = __float2half_rn(0.f);
        hbuf[1][tid] = __float2half_rn(0.f);
    }
    float c = 0.f;
    __syncthreads();

    const float* xp = g_xpart + e * G4 + grow;    // step stride = E*G4
    float* th = g_trueh + e;
    float4* gq = (float4*)(gwarp + w * 32);       // 8 quads per warp

    float xv_next = __ldg(xp);                    // prefetch t=0

    int p = 0;
    #pragma unroll 1
    for (int t = 0; t < B; t++) {
        float xv = xv_next;
        int tn = (t + 1 < B) ? (t + 1) : (B - 1);
        xv_next = __ldg(xp + tn * (E * G4));

        const float4* hvec = (const float4*)hbuf[p];
        __half2 z = __floats2half2_rn(0.f, 0.f);
        __half2 a0 = z, a1 = z, a2 = z, a3 = z;
        #pragma unroll
        for (int j = 0; j < 13; j++) {
            float4 hv = hvec[j];
            a0 = __hfma2(w2[4 * j + 0], *(__half2*)&hv.x, a0);
            a1 = __hfma2(w2[4 * j + 1], *(__half2*)&hv.y, a1);
            a2 = __hfma2(w2[4 * j + 2], *(__half2*)&hv.z, a2);
            a3 = __hfma2(w2[4 * j + 3], *(__half2*)&hv.w, a3);
        }
        __half2 s = __hadd2(__hadd2(a0, a1), __hadd2(a2, a3));
        float2 fs = __half22float2(s);
        float pre = (fs.x + fs.y) + xv;
        float a = (gt == 2) ? tanhapx(pre) : sigt(pre);

        gwarp[w * 32 + lane] = a;
        __syncwarp();
        float4 gv = gq[uiw];          // (i, f, g, o) of this unit

        c = gv.y * c + gv.x * gv.z;
        float hval = gv.w * tanhapx(c);

        if (gt == 0 && valid) {
            hbuf[p ^ 1][u] = __float2half_rn(hval);
            if (u == last_s[t]) th[t * E] = hval;
        }
        __syncthreads();
        p ^= 1;
    }
}

// ---------------- K4: final FC + sigmoid ----------------
__global__ void k_fc(const float* __restrict__ fcw,
                     const float* __restrict__ fcb,
                     float* __restrict__ out) {
    int warp = (blockIdx.x * blockDim.x + threadIdx.x) >> 5;
    int lane = threadIdx.x & 31;
    if (warp >= B) return;
    const float* th = g_trueh + warp * E;
    float acc = 0.f;
    #pragma unroll
    for (int k = 0; k < 4; k++) acc += th[lane + 32 * k] * fcw[lane + 32 * k];
    #pragma unroll
    for (int s = 16; s > 0; s >>= 1) acc += __shfl_down_sync(0xFFFFFFFFu, acc, s);
    if (lane == 0) out[warp] = sigt(acc + fcb[0]);
}

// ---------------- launcher: kernel launches ONLY ----------------
extern "C" void kernel_launch(void* const* d_in, const int* in_sizes, int n_in,
                              void* d_out, int out_size) {
    const int*   diag = (const int*)d_in[0];
    const float* mask = (const float*)d_in[1];
    const float* tab  = (const float*)d_in[2];
    const float* Wih  = (const float*)d_in[3];
    const float* Whh  = (const float*)d_in[4];
    const float* bih  = (const float*)d_in[5];
    const float* bhh  = (const float*)d_in[6];
    const float* fcw  = (const float*)d_in[7];
    const float* fcb  = (const float*)d_in[8];
    float* out = (float*)d_out;

    (void)in_sizes; (void)n_in; (void)out_size;

    k_embed<<<(B * V) / 8, 256>>>(diag, mask, tab);
    k_gemm<<<dim3(M_TOT / BMg, G4 / BNg), 256>>>(Wih, bih, bhh);
    k_rec<<<E, 416>>>(Whh);
    k_fc<<<32, 256>>>(fcw, fcb, out);
}

// round 12
// speedup vs baseline: 1.5447x; 1.0139x over previous
#include <cuda_runtime.h>
#include <cuda_fp16.h>
#include <cuda_bf16.h>
#include <math.h>

// Problem constants
#define B     256
#define V     100
#define C     40
#define E     128
#define H     100
#define G4    400      // 4*H
#define M_TOT 32768    // B*E

// ---------------- device scratch ----------------
__device__ int   g_last[B];                          // built via atomicMax (idempotent)
__device__ __align__(16) float g_xseq[B * V * E];    // A[32768][100]
__device__ __align__(16) float g_xpart[M_TOT * G4];  // x @ W_ih^T + biases
__device__ float g_trueh[B * E];

// ---------------- helpers ----------------
__device__ __forceinline__ unsigned f2tf32(float f) {
    unsigned r;
    asm("cvt.rna.tf32.f32 %0, %1;" : "=r"(r) : "f"(f));
    return r;
}
__device__ __forceinline__ void mma8(float* d, const unsigned* a,
                                     unsigned b0, unsigned b1) {
    asm("mma.sync.aligned.m16n8k8.row.col.f32.tf32.tf32.f32 "
        "{%0,%1,%2,%3},{%4,%5,%6,%7},{%8,%9},{%0,%1,%2,%3};"
        : "+f"(d[0]), "+f"(d[1]), "+f"(d[2]), "+f"(d[3])
        : "r"(a[0]), "r"(a[1]), "r"(a[2]), "r"(a[3]), "r"(b0), "r"(b1));
}
__device__ __forceinline__ float tanhapx(float x) {
    float r;
    asm("tanh.approx.f32 %0, %1;" : "=f"(r) : "f"(x));
    return r;
}
__device__ __forceinline__ float sigt(float x) {
    return fmaf(0.5f, tanhapx(0.5f * x), 0.5f);
}

// ---------------- K1: masked embedding sum + fused last-visit ----------
__global__ void k_embed(const int* __restrict__ diag,
                        const float* __restrict__ mask,
                        const float* __restrict__ table) {
    int flag = 0;
    if (threadIdx.x < 64) flag = diag[2 * threadIdx.x + 1];
    int is64 = __syncthreads_or(flag != 0) ? 0 : 1;

    int p    = blockIdx.x * 8 + (threadIdx.x >> 5);   // (b*V + v)
    int lane = threadIdx.x & 31;
    int b    = p / V;
    int v    = p - b * V;
    const float4* tab4 = (const float4*)table;
    float4 acc = make_float4(0.f, 0.f, 0.f, 0.f);
    bool has = false;
    int base = p * C;
    #pragma unroll
    for (int c4 = 0; c4 < C / 4; c4++) {
        float4 m4 = *(const float4*)(mask + base + c4 * 4);
        int code[4];
        #pragma unroll
        for (int q = 0; q < 4; q++)
            code[q] = diag[(base + c4 * 4 + q) << is64];
        float mm[4] = {m4.x, m4.y, m4.z, m4.w};
        #pragma unroll
        for (int q = 0; q < 4; q++) {
            has |= (mm[q] != 0.f);
            float4 t = tab4[code[q] * 32 + lane];
            acc.x += t.x * mm[q]; acc.y += t.y * mm[q];
            acc.z += t.z * mm[q]; acc.w += t.w * mm[q];
        }
    }
    ((float4*)g_xseq)[p * 32 + lane] = acc;
    if (lane == 0 && has) atomicMax(&g_last[b], v);
}

// ---------------- K2: single-TF32 tensor GEMM ----------------
#define BMg 128
#define BNg 80
#define SST 36

__global__ void __launch_bounds__(256, 2) k_gemm(const float* __restrict__ W,
                                                 const float* __restrict__ bih,
                                                 const float* __restrict__ bhh) {
    __shared__ unsigned As[BMg * SST];
    __shared__ unsigned Ws[BNg * SST];

    int tid = threadIdx.x;
    int wid = tid >> 5, lane = tid & 31;
    int wm = wid & 3, wn = wid >> 2;
    int g = lane >> 2, t = lane & 3;
    int m0 = blockIdx.x * BMg;
    int n0 = blockIdx.y * BNg;

    float d[2][5][4];
    #pragma unroll
    for (int ni = 0; ni < 5; ni++) {
        int cc = n0 + wn * 40 + ni * 8 + 2 * t;
        float b0 = bih[cc] + bhh[cc];
        float b1 = bih[cc + 1] + bhh[cc + 1];
        #pragma unroll
        for (int mi = 0; mi < 2; mi++) {
            d[mi][ni][0] = b0; d[mi][ni][1] = b1;
            d[mi][ni][2] = b0; d[mi][ni][3] = b1;
        }
    }

    #pragma unroll 1
    for (int kc = 0; kc < 4; kc++) {
        int k0 = kc * 32;
        #pragma unroll
        for (int i = 0; i < 16; i++) {
            int li = i * 256 + tid;
            int m = li >> 5, k = li & 31;
            float v = (k0 + k < 100) ? g_xseq[(m0 + m) * 100 + k0 + k] : 0.f;
            As[m * SST + k] = f2tf32(v);
        }
        #pragma unroll
        for (int i = 0; i < 10; i++) {
            int li = i * 256 + tid;
            int n = li >> 5, k = li & 31;
            float w = (k0 + k < 100) ? W[(n0 + n) * 100 + k0 + k] : 0.f;
            Ws[n * SST + k] = f2tf32(w);
        }
        __syncthreads();

        int ns = (kc == 3) ? 1 : 4;
        #pragma unroll
        for (int s = 0; s < 4; s++) {
            if (s >= ns) break;
            unsigned a[2][4];
            #pragma unroll
            for (int mi = 0; mi < 2; mi++) {
                int r = (wm * 32 + mi * 16 + g) * SST + s * 8 + t;
                a[mi][0] = As[r];
                a[mi][1] = As[r + 8 * SST];
                a[mi][2] = As[r + 4];
                a[mi][3] = As[r + 8 * SST + 4];
            }
            #pragma unroll
            for (int ni = 0; ni < 5; ni++) {
                int rb = (wn * 40 + ni * 8 + g) * SST + s * 8 + t;
                unsigned b0 = Ws[rb], b1 = Ws[rb + 4];
                #pragma unroll
                for (int mi = 0; mi < 2; mi++)
                    mma8(d[mi][ni], a[mi], b0, b1);
            }
        }
        __syncthreads();
    }

    #pragma unroll
    for (int mi = 0; mi < 2; mi++) {
        int r = m0 + wm * 32 + mi * 16 + g;
        #pragma unroll
        for (int ni = 0; ni < 5; ni++) {
            int cc = n0 + wn * 40 + ni * 8 + 2 * t;
            *(float2*)&g_xpart[r * G4 + cc]       = make_float2(d[mi][ni][0], d[mi][ni][1]);
            *(float2*)&g_xpart[(r + 8) * G4 + cc] = make_float2(d[mi][ni][2], d[mi][ni][3]);
        }
    }
}

// ---------------- K3: in-warp-unit fp16 recurrence, BRANCH-FREE step -----
// 416 thr = 13 warps. Warp w owns units 8w..8w+7; lane = uiw*4 + gt.
// Gate exchange: STS + syncwarp + broadcast LDS.128 (measured best).
// Step body has NO divergent branches:
//  - activation = Sc*tanh(Sc*pre) + Bc with per-thread constants
//  - hbuf store unconditional from all 4 quad lanes (same addr, same value);
//    invalid units write the pad, which is multiplied by zero weights.
__global__ void __launch_bounds__(416, 1) k_rec(const float* __restrict__ Whh) {
    __shared__ __align__(16) __half hbuf[2][104];   // h[0..99] + pad (content x0 = harmless)
    __shared__ __align__(16) float  gwarp[416];     // per-warp gate slots
    __shared__ int last_s[B];

    int tid  = threadIdx.x;
    int e    = blockIdx.x;
    int w    = tid >> 5;
    int lane = tid & 31;
    int uiw  = lane >> 2;             // unit-in-warp 0..7
    int gt   = lane & 3;              // 0=i 1=f 2=g 3=o
    int u    = w * 8 + uiw;           // unit 0..103 (valid < 100)
    bool valid = (u < H);
    int grow = gt * H + (valid ? u : (H - 1));   // clamped gate row

    // activation constants: sigmoid = 0.5*tanh(0.5x)+0.5 ; tanh = 1*tanh(1x)+0
    float Sc = (gt == 2) ? 1.f : 0.5f;
    float Bc = (gt == 2) ? 0.f : 0.5f;

    // 52 half2 weight regs (zeros if invalid/pad)
    __half2 w2[52];
    #pragma unroll
    for (int j = 0; j < 50; j++) {
        float lo = 0.f, hi = 0.f;
        if (valid) {
            lo = Whh[grow * 100 + 2 * j];
            hi = Whh[grow * 100 + 2 * j + 1];
        }
        w2[j] = __floats2half2_rn(lo, hi);
    }
    w2[50] = __floats2half2_rn(0.f, 0.f);
    w2[51] = __floats2half2_rn(0.f, 0.f);

    for (int i = tid; i < B; i += 416) last_s[i] = g_last[i];
    if (tid < 104) {
        hbuf[0][tid] = __float2half_rn(0.f);
        hbuf[1][tid] = __float2half_rn(0.f);
    }
    float c = 0.f;
    __syncthreads();

    const float* xp = g_xpart + e * G4 + grow;    // step stride = E*G4
    float* th = g_trueh + e;
    float4* gq = (float4*)(gwarp + w * 32);       // 8 quads per warp

    float xv_next = __ldg(xp);                    // prefetch t=0

    int p = 0;
    #pragma unroll 1
    for (int t = 0; t < B; t++) {
        float xv = xv_next;
        int tn = (t + 1 < B) ? (t + 1) : (B - 1);
        xv_next = __ldg(xp + tn * (E * G4));

        const float4* hvec = (const float4*)hbuf[p];
        __half2 z = __floats2half2_rn(0.f, 0.f);
        __half2 a0 = z, a1 = z, a2 = z, a3 = z;
        #pragma unroll
        for (int j = 0; j < 13; j++) {
            float4 hv = hvec[j];
            a0 = __hfma2(w2[4 * j + 0], *(__half2*)&hv.x, a0);
            a1 = __hfma2(w2[4 * j + 1], *(__half2*)&hv.y, a1);
            a2 = __hfma2(w2[4 * j + 2], *(__half2*)&hv.z, a2);
            a3 = __hfma2(w2[4 * j + 3], *(__half2*)&hv.w, a3);
        }
        __half2 s = __hadd2(__hadd2(a0, a1), __hadd2(a2, a3));
        float2 fs = __half22float2(s);
        float pre = (fs.x + fs.y) + xv;
        float a = fmaf(Sc, tanhapx(Sc * pre), Bc);   // branchless activation

        gwarp[w * 32 + lane] = a;
        __syncwarp();
        float4 gv = gq[uiw];          // (i, f, g, o) of this unit

        c = gv.y * c + gv.x * gv.z;
        float hval = gv.w * tanhapx(c);

        // unconditional: 4 lanes write same value to same address;
        // invalid units hit the pad (weights there are zero).
        hbuf[p ^ 1][u] = __float2half_rn(hval);
        if (gt == 0 && u == last_s[t]) th[t * E] = hval;   // single @P STG

        __syncthreads();
        p ^= 1;
    }
}

// ---------------- K4: final FC + sigmoid ----------------
__global__ void k_fc(const float* __restrict__ fcw,
                     const float* __restrict__ fcb,
                     float* __restrict__ out) {
    int warp = (blockIdx.x * blockDim.x + threadIdx.x) >> 5;
    int lane = threadIdx.x & 31;
    if (warp >= B) return;
    const float* th = g_trueh + warp * E;
    float acc = 0.f;
    #pragma unroll
    for (int k = 0; k < 4; k++) acc += th[lane + 32 * k] * fcw[lane + 32 * k];
    #pragma unroll
    for (int s = 16; s > 0; s >>= 1) acc += __shfl_down_sync(0xFFFFFFFFu, acc, s);
    if (lane == 0) out[warp] = sigt(acc + fcb[0]);
}

// ---------------- launcher: kernel launches ONLY ----------------
extern "C" void kernel_launch(void* const* d_in, const int* in_sizes, int n_in,
                              void* d_out, int out_size) {
    const int*   diag = (const int*)d_in[0];
    const float* mask = (const float*)d_in[1];
    const float* tab  = (const float*)d_in[2];
    const float* Wih  = (const float*)d_in[3];
    const float* Whh  = (const float*)d_in[4];
    const float* bih  = (const float*)d_in[5];
    const float* bhh  = (const float*)d_in[6];
    const float* fcw  = (const float*)d_in[7];
    const float* fcb  = (const float*)d_in[8];
    float* out = (float*)d_out;

    (void)in_sizes; (void)n_in; (void)out_size;

    k_embed<<<(B * V) / 8, 256>>>(diag, mask, tab);
    k_gemm<<<dim3(M_TOT / BMg, G4 / BNg), 256>>>(Wih, bih, bhh);
    k_rec<<<E, 416>>>(Whh);
    k_fc<<<32, 256>>>(fcw, fcb, out);
}